// round 15
// baseline (speedup 1.0000x reference)
#include <cuda_runtime.h>
#include <cuda_fp16.h>
#include <cstdint>

// Problem constants (fixed by the dataset)
#define B_  2
#define L_  192
#define D_  768
#define NC_ 4
#define H_  256

#define KCH     64              // k per chunk in refine
#define NCHUNK  4               // K = 256 = 4 x 64 (bs tail folded into epilogue)
#define NTHR    256             // refine threads (8 warps), 2 CTAs/SM
#define ROWB    144             // padded row stride: 64 fp16 = 128B + 16B pad

#define WIMG_BYTES (256 * ROWB) // one W image: 256 n-rows x 144B

// Refine SMEM layout (byte offsets into dynamic smem) -- 97KB => 2 CTAs/SM
#define OXB(buf)  ((buf) * 9216)             // X bufs (fp16, 64 rows)
#define OWB(buf)  (18432 + (buf) * 36864)    // W bufs (fp16, single image)
#define OBMID     92160
#define OWOUT     93184
#define OWTAIL    94208                       // float[4][256]
#define OPART     98304                       // float[64][4]
#define SMEM_BYTES 99328

#define PROJ_BLOCKS 240   // 12 m-tiles x 20 n-tiles (32x64 tiles)
#define PREP_BLOCKS (PROJ_BLOCKS + 32)
#define PKC 64            // proj k-chunk

// Scratch (no cudaMalloc allowed)
__device__ float g_hp[B_ * L_ * H_];                 // [B*L, H]
__device__ float g_ha[B_ * L_ * NC_ * H_];           // [B*L, NC*H]
__device__ __align__(16) char g_w_img[NC_ * NCHUNK * WIMG_BYTES];

// ---------------------------------------------------------------------------
// Helpers
// ---------------------------------------------------------------------------
__device__ __forceinline__ float htanh(float x) {
    float y;
    asm("tanh.approx.f32 %0, %1;" : "=f"(y) : "f"(x));
    return y;
}

__device__ __forceinline__ uint32_t f16pack(float a, float b) {
    const __half2 h = __floats2half2_rn(a, b);
    return *(const uint32_t*)&h;
}

__device__ __forceinline__ unsigned long long pack2(float x) {
    unsigned long long r;
    asm("mov.b64 %0, {%1, %1};" : "=l"(r) : "f"(x));
    return r;
}
__device__ __forceinline__ unsigned long long ffma2(unsigned long long a,
                                                    unsigned long long b,
                                                    unsigned long long c) {
    unsigned long long d;
    asm("fma.rn.f32x2 %0, %1, %2, %3;" : "=l"(d) : "l"(a), "l"(b), "l"(c));
    return d;
}
__device__ __forceinline__ void unpack2(unsigned long long v, float& lo, float& hi) {
    asm("mov.b64 {%0, %1}, %2;" : "=f"(lo), "=f"(hi) : "l"(v));
}

__device__ __forceinline__ void cp_async16(uint32_t smem, const void* gptr) {
    asm volatile("cp.async.cg.shared.global [%0], [%1], 16;" :: "r"(smem), "l"(gptr));
}
__device__ __forceinline__ void cp_commit() { asm volatile("cp.async.commit_group;"); }
__device__ __forceinline__ void cp_wait_all() { asm volatile("cp.async.wait_group 0;" ::: "memory"); }

__device__ __forceinline__ void sts64(uint32_t addr, uint32_t r0, uint32_t r1) {
    asm volatile("st.shared.v2.b32 [%0], {%1, %2};"
                 :: "r"(addr), "r"(r0), "r"(r1) : "memory");
}

__device__ __forceinline__ void ldsm4(uint32_t* r, uint32_t addr) {
    asm volatile("ldmatrix.sync.aligned.m8n8.x4.shared.b16 {%0,%1,%2,%3}, [%4];"
                 : "=r"(r[0]), "=r"(r[1]), "=r"(r[2]), "=r"(r[3]) : "r"(addr));
}

__device__ __forceinline__ void mma16816(float* d, const uint32_t* a, const uint32_t* b) {
    asm volatile("mma.sync.aligned.m16n8k16.row.col.f32.f16.f16.f32 "
                 "{%0,%1,%2,%3}, {%4,%5,%6,%7}, {%8,%9}, {%0,%1,%2,%3};"
                 : "+f"(d[0]), "+f"(d[1]), "+f"(d[2]), "+f"(d[3])
                 : "r"(a[0]), "r"(a[1]), "r"(a[2]), "r"(a[3]),
                   "r"(b[0]), "r"(b[1]));
}

// ---------------------------------------------------------------------------
// Kernel 1 (fused): proj (blocks 0..239) + wsplit (blocks 240..271)
// proj: 32x64 tiles, KC=64, fully cp.async double-buffered (A and B).
// ---------------------------------------------------------------------------
__global__ __launch_bounds__(256) void prep_kernel(
    const float* __restrict__ seq,
    const float* __restrict__ Wp, const float* __restrict__ bp,
    const float* __restrict__ Wa, const float* __restrict__ ba,
    const float* __restrict__ Wmid)
{
    const int tid = threadIdx.x;
    const int bx = blockIdx.x;

    if (bx >= PROJ_BLOCKS) {
        // ---- wsplit: fp16 image, rows padded to 144B ----
        const int idx = bx - PROJ_BLOCKS;
        const int n = idx >> 3, c = (idx >> 1) & 3, half = idx & 1;
        const int j = tid;
        char* img = g_w_img + (size_t)(n * NCHUNK + c) * WIMG_BYTES;
#pragma unroll 1
        for (int kp = half * 16; kp < half * 16 + 16; kp++) {
            const int k0 = c * KCH + kp * 2;
            const float w0 = Wmid[(n * (H_ + NC_) + k0    ) * H_ + j];
            const float w1 = Wmid[(n * (H_ + NC_) + k0 + 1) * H_ + j];
            *(uint32_t*)(img + j * ROWB + kp * 4) = f16pack(w0, w1);
        }
        if (half == 0)
            *(uint4*)(img + j * ROWB + 128) = make_uint4(0, 0, 0, 0);
        return;
    }

    // ---- proj: tile 32(m) x 64(n), KC=64, double-buffered cp.async ----
    __shared__ __align__(16) float As[2][32][72];   // [buf][m][k] pad->2-way max
    __shared__ __align__(16) float Bs[2][PKC][64];  // [buf][k][n]

    const int tx = tid & 15;        // n quad: cols tx*4
    const int ty = tid >> 4;        // m pair: rows ty*2, ty*2+1
    const int m0 = (bx / 20) * 32;
    const int n0 = (bx % 20) * 64;

    const float* Wsrc;
    int ld, coff;
    if (n0 < H_) { Wsrc = Wp; ld = H_;        coff = n0; }
    else         { Wsrc = Wa; ld = NC_ * H_;  coff = n0 - H_; }

    // A copy: 32 rows x 64 k = 512 x 16B chunks -> 2/thread
    // B copy: 64 k x 64 n = 1024 x 16B chunks -> 4/thread
    auto copyAB = [&](int kc, int buf) {
        const uint32_t dstA = (uint32_t)__cvta_generic_to_shared(&As[buf][0][0]);
        const uint32_t dstB = (uint32_t)__cvta_generic_to_shared(&Bs[buf][0][0]);
#pragma unroll
        for (int i = 0; i < 2; i++) {
            const int e = i * 256 + tid;
            const int row = e >> 4, c4 = e & 15;
            cp_async16(dstA + (uint32_t)(row * 72 * 4 + c4 * 16),
                       seq + (size_t)(m0 + row) * D_ + kc + c4 * 4);
        }
#pragma unroll
        for (int i = 0; i < 4; i++) {
            const int e = i * 256 + tid;
            const int row = e >> 4, c4 = e & 15;
            cp_async16(dstB + (uint32_t)(row * 256 + c4 * 16),
                       Wsrc + (size_t)(kc + row) * ld + coff + c4 * 4);
        }
        cp_commit();
    };

    unsigned long long acc2[2][2];
#pragma unroll
    for (int i = 0; i < 2; i++) { acc2[i][0] = 0ull; acc2[i][1] = 0ull; }

    copyAB(0, 0);
    cp_wait_all();
    __syncthreads();

#pragma unroll 1
    for (int c = 0; c < D_ / PKC; c++) {
        const int buf = c & 1;
        if (c < D_ / PKC - 1) copyAB((c + 1) * PKC, buf ^ 1);
#pragma unroll
        for (int k = 0; k < PKC; k++) {
            const float a0 = As[buf][ty * 2][k];
            const float a1 = As[buf][ty * 2 + 1][k];
            const ulonglong2 b2 = *(const ulonglong2*)&Bs[buf][k][tx * 4];
            const unsigned long long p0v = pack2(a0);
            const unsigned long long p1v = pack2(a1);
            acc2[0][0] = ffma2(p0v, b2.x, acc2[0][0]);
            acc2[0][1] = ffma2(p0v, b2.y, acc2[0][1]);
            acc2[1][0] = ffma2(p1v, b2.x, acc2[1][0]);
            acc2[1][1] = ffma2(p1v, b2.y, acc2[1][1]);
        }
        if (c < D_ / PKC - 1) {
            cp_wait_all();
            __syncthreads();
        }
    }

#pragma unroll
    for (int i = 0; i < 2; i++) {
        const int r = m0 + ty * 2 + i;
#pragma unroll
        for (int j = 0; j < 2; j++) {
            float lo, hi;
            unpack2(acc2[i][j], lo, hi);
            const int cg = n0 + tx * 4 + j * 2;
            if (cg < H_) {
                g_hp[r * H_ + cg] = lo + bp[cg];
                g_hp[r * H_ + cg + 1] = hi + bp[cg + 1];
            } else {
                const int c2 = cg - H_;
                g_ha[r * (NC_ * H_) + c2] = lo + ba[c2];
                g_ha[r * (NC_ * H_) + c2 + 1] = hi + ba[c2 + 1];
            }
        }
    }
}

// ---------------------------------------------------------------------------
// Kernel 2: refinement via mma.sync m16n8k16 fp16 (X and W single fp16).
// Block (b, n, 4p x 16a): D[64,256] = X[64,256] @ W[256,256] + bs-tail (epi).
// 256 threads = 8 warps, 2(M)x4(N), warp tile 32x64. 2 CTAs/SM.
// ---------------------------------------------------------------------------
__global__ __launch_bounds__(NTHR, 2) void refine_kernel(
    const float* __restrict__ bscore,   // [B, L, NC, L]
    const float* __restrict__ Wmid,     // [NC, H+NC, H]
    const float* __restrict__ bmid,     // [NC, H]
    const float* __restrict__ Wout,     // [NC, H]
    float* __restrict__ out)            // [B, L, NC, L]
{
    extern __shared__ __align__(16) char sm[];
    const uint32_t base = (uint32_t)__cvta_generic_to_shared(sm);

    float* bmid_s  = (float*)(sm + OBMID);
    float* wout_s  = (float*)(sm + OWOUT);
    float* wtail_s = (float*)(sm + OWTAIL);  // [4][256]
    float* part_s  = (float*)(sm + OPART);   // [64][4]

    const int tid = threadIdx.x;
    const int wid = tid >> 5;
    const int lane = tid & 31;
    const int bz = blockIdx.z;
    const int b = bz >> 2, n = bz & 3;
    const int p0 = blockIdx.y * 4;
    const int a0 = blockIdx.x * 16;

    const int mwarp = (wid & 1) * 32;
    const int nwarp = (wid >> 1) * 64;

    // producer group: wid>>1 -> 4 groups of 2 warps
    const int group = wid >> 1;

    // epilogue tables
    bmid_s[tid] = bmid[n * H_ + tid];
    wout_s[tid] = Wout[n * H_ + tid];
#pragma unroll
    for (int q = 0; q < 4; q++) {
        const int i = q * NTHR + tid;
        wtail_s[i] = Wmid[(n * (H_ + NC_) + H_ + (i >> 8)) * H_ + (i & 255)];
    }

    // coalesced build mapping: group = 64 threads, 4 lanes per row,
    // 4 passes of 16 rows. Each lane covers 4 consecutive k.
    const int gt = (wid & 1) * 32 + lane;   // 0..63 within group
    const int brow0 = gt >> 2;              // 0..15 (pass adds 16*pp)
    const int bk4 = (gt & 3) * 4;
    const float* hp_base = g_hp + (b * L_) * H_;
    const float* ha_base = g_ha + (b * L_ * NC_ + n) * H_;

    // lane-constant ldmatrix address offsets
    const uint32_t a_off = (uint32_t)((mwarp + (lane & 15)) * ROWB + ((lane >> 4) << 4));
    const uint32_t b_off = (uint32_t)((nwarp + (lane & 7) + ((lane & 16) ? 8 : 0)) * ROWB
                                      + ((lane & 8) ? 16 : 0));

    // build 16 k-values of chunk c at k-offset qoff into buffer buf
    auto buildX_part = [&](int c, int buf, int qoff) {
        const int kg = c * KCH + qoff + bk4;
#pragma unroll
        for (int pp = 0; pp < 4; pp++) {
            const int row = pp * 16 + brow0;     // 0..63
            const int p = p0 + (row >> 4);
            const int a = a0 + (row & 15);
            const float4 u = *(const float4*)(hp_base + p * H_ + kg);
            const float4 v = *(const float4*)(ha_base + a * (NC_ * H_) + kg);
            const float x0 = htanh(u.x + v.x);
            const float x1 = htanh(u.y + v.y);
            const float x2 = htanh(u.z + v.z);
            const float x3 = htanh(u.w + v.w);
            sts64(base + OXB(buf) + (uint32_t)(row * ROWB + (qoff + bk4) * 2),
                  f16pack(x0, x1), f16pack(x2, x3));
        }
    };

    auto copyW = [&](int c, int buf) {
        const char* src = g_w_img + (size_t)(n * NCHUNK + c) * WIMG_BYTES;
        const uint32_t dst = base + OWB(buf);
#pragma unroll
        for (int i = 0; i < 9; i++) {
            const int e = i * NTHR + tid;           // 2304 x 16B
            cp_async16(dst + e * 16, src + (size_t)e * 16);
        }
        cp_commit();
    };

    float acc[2][8][4];
#pragma unroll
    for (int t = 0; t < 2; t++)
#pragma unroll
        for (int q = 0; q < 8; q++)
#pragma unroll
            for (int r = 0; r < 4; r++) acc[t][q][r] = 0.0f;

    // one k16-step: 16 independent MMAs
    auto mma_ks = [&](int ks, uint32_t xb, uint32_t wb) {
        uint32_t A0[4], A1[4], BH[4][4];
        const uint32_t kb = (uint32_t)(ks * 32);
        ldsm4(A0, xb + a_off + kb);
        ldsm4(A1, xb + a_off + 16 * ROWB + kb);
#pragma unroll
        for (int q = 0; q < 4; q++)
            ldsm4(BH[q], wb + b_off + q * 16 * ROWB + kb);
#pragma unroll
        for (int q2 = 0; q2 < 8; q2++) {
            const uint32_t* bq = &BH[q2 >> 1][(q2 & 1) * 2];
            mma16816(acc[0][q2], A0, bq);
            mma16816(acc[1][q2], A1, bq);
        }
    };

    // ---- prologue: each group builds its quarter of chunk 0 ----
    copyW(0, 0);
    buildX_part(0, 0, group * 16);
    cp_wait_all();
    __syncthreads();

#pragma unroll 1
    for (int c = 0; c < NCHUNK; c++) {
        const int cur = c & 1;
        const uint32_t xb = base + OXB(cur);
        const uint32_t wb = base + OWB(cur);
        const bool more = (c < NCHUNK - 1);
        if (more) copyW(c + 1, cur ^ 1);
        mma_ks(0, xb, wb);
        if (more && group == 0) buildX_part(c + 1, cur ^ 1, 0);
        mma_ks(1, xb, wb);
        if (more && group == 1) buildX_part(c + 1, cur ^ 1, 16);
        if (more && group == 3) buildX_part(c + 1, cur ^ 1, 48);
        mma_ks(2, xb, wb);
        if (more && group == 2) buildX_part(c + 1, cur ^ 1, 32);
        mma_ks(3, xb, wb);
        if (more) {
            cp_wait_all();
            __syncthreads();
        }
    }

    // ---- epilogue: +bs-tail +bmid, tanh, dot Wout, reduce over N ----
    const int g = lane >> 2;
    float bsv[2][2][4];
#pragma unroll
    for (int t = 0; t < 2; t++)
#pragma unroll
        for (int h = 0; h < 2; h++) {
            const int row = mwarp + t * 16 + g + h * 8;
            const float* bsp = bscore
                + ((b * L_ + p0 + (row >> 4)) * NC_) * L_ + a0 + (row & 15);
#pragma unroll
            for (int ct = 0; ct < 4; ct++) bsv[t][h][ct] = bsp[ct * L_];
        }

    float part[2][2] = {{0.0f, 0.0f}, {0.0f, 0.0f}};
#pragma unroll
    for (int q2 = 0; q2 < 8; q2++) {
        const int j0 = nwarp + q2 * 8 + (lane & 3) * 2;
        const float bm0 = bmid_s[j0], bm1 = bmid_s[j0 + 1];
        const float wo0 = wout_s[j0], wo1 = wout_s[j0 + 1];
        float wt0[4], wt1[4];
#pragma unroll
        for (int ct = 0; ct < 4; ct++) {
            wt0[ct] = wtail_s[ct * 256 + j0];
            wt1[ct] = wtail_s[ct * 256 + j0 + 1];
        }
#pragma unroll
        for (int t = 0; t < 2; t++)
#pragma unroll
            for (int h = 0; h < 2; h++) {
                float v0 = acc[t][q2][h * 2 + 0] + bm0;
                float v1 = acc[t][q2][h * 2 + 1] + bm1;
#pragma unroll
                for (int ct = 0; ct < 4; ct++) {
                    v0 = fmaf(bsv[t][h][ct], wt0[ct], v0);
                    v1 = fmaf(bsv[t][h][ct], wt1[ct], v1);
                }
                part[t][h] = fmaf(htanh(v0), wo0, part[t][h]);
                part[t][h] = fmaf(htanh(v1), wo1, part[t][h]);
            }
    }
#pragma unroll
    for (int t = 0; t < 2; t++)
#pragma unroll
        for (int h = 0; h < 2; h++) {
            float v = part[t][h];
            v += __shfl_xor_sync(0xFFFFFFFFu, v, 1, 4);
            v += __shfl_xor_sync(0xFFFFFFFFu, v, 2, 4);
            if ((lane & 3) == 0) {
                const int row = mwarp + t * 16 + g + h * 8;
                part_s[row * 4 + (wid >> 1)] = v;
            }
        }
    __syncthreads();

    if (tid < 64) {
        const float s = part_s[tid * 4] + part_s[tid * 4 + 1]
                      + part_s[tid * 4 + 2] + part_s[tid * 4 + 3];
        const int p = p0 + (tid >> 4);
        const int a = a0 + (tid & 15);
        out[((b * L_ + p) * NC_ + n) * L_ + a] = s;
    }
}

// ---------------------------------------------------------------------------
// Launch
// ---------------------------------------------------------------------------
extern "C" void kernel_launch(void* const* d_in, const int* in_sizes, int n_in,
                              void* d_out, int out_size) {
    const float* seq    = (const float*)d_in[0];
    const float* bscore = (const float*)d_in[1];
    const float* Wp     = (const float*)d_in[2];
    const float* bp     = (const float*)d_in[3];
    const float* Wa     = (const float*)d_in[4];
    const float* ba     = (const float*)d_in[5];
    const float* Wmid   = (const float*)d_in[6];
    const float* bmid   = (const float*)d_in[7];
    const float* Wout   = (const float*)d_in[8];
    float* out = (float*)d_out;

    prep_kernel<<<PREP_BLOCKS, 256>>>(seq, Wp, bp, Wa, ba, Wmid);

    cudaFuncSetAttribute(refine_kernel,
                         cudaFuncAttributeMaxDynamicSharedMemorySize, SMEM_BYTES);
    refine_kernel<<<dim3(L_ / 16, L_ / 4, B_ * NC_), NTHR, SMEM_BYTES>>>(
        bscore, Wmid, bmid, Wout, out);
}

// round 16
// speedup vs baseline: 1.0519x; 1.0519x over previous
#include <cuda_runtime.h>
#include <cuda_fp16.h>
#include <cstdint>

// Problem constants (fixed by the dataset)
#define B_  2
#define L_  192
#define D_  768
#define NC_ 4
#define H_  256

#define KCH     64              // k per chunk in refine
#define NCHUNK  4               // K = 256 = 4 x 64 (bs tail folded into epilogue)
#define NTHR    256             // refine threads (8 warps), 2 CTAs/SM
#define ROWB    144             // padded row stride: 64 fp16 = 128B + 16B pad

#define WIMG_BYTES (256 * ROWB) // one W image: 256 n-rows x 144B

// Refine SMEM layout (byte offsets into dynamic smem) -- 97KB => 2 CTAs/SM
#define OXB(buf)  ((buf) * 9216)             // X bufs (fp16, 64 rows)
#define OWB(buf)  (18432 + (buf) * 36864)    // W bufs (fp16, single image)
#define OBMID     92160
#define OWOUT     93184
#define OWTAIL    94208                       // float[4][256]
#define OPART     98304                       // float[64][4]
#define SMEM_BYTES 99328

#define PROJ_BLOCKS 120   // 6 m-tiles x 20 n-tiles (64x64 tiles)
#define PREP_BLOCKS (PROJ_BLOCKS + 32)

// Scratch (no cudaMalloc allowed)
__device__ float g_hp[B_ * L_ * H_];                 // [B*L, H]
__device__ float g_ha[B_ * L_ * NC_ * H_];           // [B*L, NC*H]
__device__ __align__(16) char g_w_img[NC_ * NCHUNK * WIMG_BYTES];

// ---------------------------------------------------------------------------
// Helpers
// ---------------------------------------------------------------------------
__device__ __forceinline__ float htanh(float x) {
    float y;
    asm("tanh.approx.f32 %0, %1;" : "=f"(y) : "f"(x));
    return y;
}

__device__ __forceinline__ uint32_t f16pack(float a, float b) {
    const __half2 h = __floats2half2_rn(a, b);
    return *(const uint32_t*)&h;
}

__device__ __forceinline__ unsigned long long pack2(float x) {
    unsigned long long r;
    asm("mov.b64 %0, {%1, %1};" : "=l"(r) : "f"(x));
    return r;
}
__device__ __forceinline__ unsigned long long ffma2(unsigned long long a,
                                                    unsigned long long b,
                                                    unsigned long long c) {
    unsigned long long d;
    asm("fma.rn.f32x2 %0, %1, %2, %3;" : "=l"(d) : "l"(a), "l"(b), "l"(c));
    return d;
}
__device__ __forceinline__ void unpack2(unsigned long long v, float& lo, float& hi) {
    asm("mov.b64 {%0, %1}, %2;" : "=f"(lo), "=f"(hi) : "l"(v));
}

__device__ __forceinline__ void cp_async16(uint32_t smem, const void* gptr) {
    asm volatile("cp.async.cg.shared.global [%0], [%1], 16;" :: "r"(smem), "l"(gptr));
}
__device__ __forceinline__ void cp_commit() { asm volatile("cp.async.commit_group;"); }
__device__ __forceinline__ void cp_wait_all() { asm volatile("cp.async.wait_group 0;" ::: "memory"); }

__device__ __forceinline__ void sts64(uint32_t addr, uint32_t r0, uint32_t r1) {
    asm volatile("st.shared.v2.b32 [%0], {%1, %2};"
                 :: "r"(addr), "r"(r0), "r"(r1) : "memory");
}

__device__ __forceinline__ void ldsm4(uint32_t* r, uint32_t addr) {
    asm volatile("ldmatrix.sync.aligned.m8n8.x4.shared.b16 {%0,%1,%2,%3}, [%4];"
                 : "=r"(r[0]), "=r"(r[1]), "=r"(r[2]), "=r"(r[3]) : "r"(addr));
}

__device__ __forceinline__ void mma16816(float* d, const uint32_t* a, const uint32_t* b) {
    asm volatile("mma.sync.aligned.m16n8k16.row.col.f32.f16.f16.f32 "
                 "{%0,%1,%2,%3}, {%4,%5,%6,%7}, {%8,%9}, {%0,%1,%2,%3};"
                 : "+f"(d[0]), "+f"(d[1]), "+f"(d[2]), "+f"(d[3])
                 : "r"(a[0]), "r"(a[1]), "r"(a[2]), "r"(a[3]),
                   "r"(b[0]), "r"(b[1]));
}

// ---------------------------------------------------------------------------
// Kernel 1 (fused): proj (blocks 0..119) + wsplit (blocks 120..151)
// (round-14 version: 64x64 tile, KC=32, ldgA register prefetch)
// ---------------------------------------------------------------------------
__global__ __launch_bounds__(256) void prep_kernel(
    const float* __restrict__ seq,
    const float* __restrict__ Wp, const float* __restrict__ bp,
    const float* __restrict__ Wa, const float* __restrict__ ba,
    const float* __restrict__ Wmid)
{
    const int tid = threadIdx.x;
    const int bx = blockIdx.x;

    if (bx >= PROJ_BLOCKS) {
        // ---- wsplit: fp16 image, rows padded to 144B ----
        const int idx = bx - PROJ_BLOCKS;
        const int n = idx >> 3, c = (idx >> 1) & 3, half = idx & 1;
        const int j = tid;
        char* img = g_w_img + (size_t)(n * NCHUNK + c) * WIMG_BYTES;
#pragma unroll 1
        for (int kp = half * 16; kp < half * 16 + 16; kp++) {
            const int k0 = c * KCH + kp * 2;
            const float w0 = Wmid[(n * (H_ + NC_) + k0    ) * H_ + j];
            const float w1 = Wmid[(n * (H_ + NC_) + k0 + 1) * H_ + j];
            *(uint32_t*)(img + j * ROWB + kp * 4) = f16pack(w0, w1);
        }
        if (half == 0)
            *(uint4*)(img + j * ROWB + 128) = make_uint4(0, 0, 0, 0);
        return;
    }

    // ---- proj: tile 64x64, KC=32, double-buffered ----
    __shared__ __align__(16) float As[2][32][68];   // [buf][k][m] padded
    __shared__ __align__(16) float Bs[2][32][64];   // [buf][k][n]

    const int tx = tid & 15;
    const int ty = tid >> 4;
    const int m0 = (bx / 20) * 64;
    const int n0 = (bx % 20) * 64;

    const float* Wsrc;
    int ld, coff;
    if (n0 < H_) { Wsrc = Wp; ld = H_;        coff = n0; }
    else         { Wsrc = Wa; ld = NC_ * H_;  coff = n0 - H_; }

    const int lm = tid >> 3;
    const int lk = (tid & 7) * 4;

    auto copyB = [&](int kc, int buf) {
        const uint32_t dst = (uint32_t)__cvta_generic_to_shared(&Bs[buf][0][0]);
#pragma unroll
        for (int i = 0; i < 2; i++) {
            const int e = i * 256 + tid;
            const int row = e >> 4, c4 = e & 15;
            cp_async16(dst + (uint32_t)(row * 256 + c4 * 16),
                       Wsrc + (size_t)(kc + row) * ld + coff + c4 * 4);
        }
        cp_commit();
    };
    auto ldgA = [&](int kc, float4* a) {
        a[0] = *(const float4*)(seq + (size_t)(m0 + lm) * D_ + kc + lk);
        a[1] = *(const float4*)(seq + (size_t)(m0 + lm + 32) * D_ + kc + lk);
    };
    auto stsA = [&](const float4* a, int buf) {
#pragma unroll
        for (int j = 0; j < 4; j++) {
            As[buf][lk + j][lm] = ((const float*)&a[0])[j];
            As[buf][lk + j][lm + 32] = ((const float*)&a[1])[j];
        }
    };

    unsigned long long acc2[4][2];
#pragma unroll
    for (int i = 0; i < 4; i++) { acc2[i][0] = 0ull; acc2[i][1] = 0ull; }

    float4 areg[2];
    copyB(0, 0);
    ldgA(0, areg);
    stsA(areg, 0);
    cp_wait_all();
    __syncthreads();

#pragma unroll 1
    for (int c = 0; c < 24; c++) {
        const int buf = c & 1;
        if (c < 23) {
            copyB((c + 1) * 32, buf ^ 1);
            ldgA((c + 1) * 32, areg);
        }
#pragma unroll
        for (int k = 0; k < 32; k++) {
            const float4 a4 = *(const float4*)&As[buf][k][ty * 4];
            const ulonglong2 b2 = *(const ulonglong2*)&Bs[buf][k][tx * 4];
            const unsigned long long pa[4] = {pack2(a4.x), pack2(a4.y),
                                              pack2(a4.z), pack2(a4.w)};
#pragma unroll
            for (int i = 0; i < 4; i++) {
                acc2[i][0] = ffma2(pa[i], b2.x, acc2[i][0]);
                acc2[i][1] = ffma2(pa[i], b2.y, acc2[i][1]);
            }
        }
        if (c < 23) {
            stsA(areg, buf ^ 1);
            cp_wait_all();
            __syncthreads();
        }
    }

#pragma unroll
    for (int i = 0; i < 4; i++) {
        const int r = m0 + ty * 4 + i;
#pragma unroll
        for (int j = 0; j < 2; j++) {
            float lo, hi;
            unpack2(acc2[i][j], lo, hi);
            const int cg = n0 + tx * 4 + j * 2;
            if (cg < H_) {
                g_hp[r * H_ + cg] = lo + bp[cg];
                g_hp[r * H_ + cg + 1] = hi + bp[cg + 1];
            } else {
                const int c2 = cg - H_;
                g_ha[r * (NC_ * H_) + c2] = lo + ba[c2];
                g_ha[r * (NC_ * H_) + c2 + 1] = hi + ba[c2 + 1];
            }
        }
    }
}

// ---------------------------------------------------------------------------
// Kernel 2: refinement via mma.sync m16n8k16 fp16 (X and W single fp16).
// Block (b, n, 4p x 16a): D[64,256] = X[64,256] @ W[256,256] + bs-tail (epi).
// 256 threads = 8 warps, 2(M)x4(N), warp tile 32x64. 2 CTAs/SM.
// buildX: ha vector hoisted (invariant across the 4 p-passes).
// ---------------------------------------------------------------------------
__global__ __launch_bounds__(NTHR, 2) void refine_kernel(
    const float* __restrict__ bscore,   // [B, L, NC, L]
    const float* __restrict__ Wmid,     // [NC, H+NC, H]
    const float* __restrict__ bmid,     // [NC, H]
    const float* __restrict__ Wout,     // [NC, H]
    float* __restrict__ out)            // [B, L, NC, L]
{
    extern __shared__ __align__(16) char sm[];
    const uint32_t base = (uint32_t)__cvta_generic_to_shared(sm);

    float* bmid_s  = (float*)(sm + OBMID);
    float* wout_s  = (float*)(sm + OWOUT);
    float* wtail_s = (float*)(sm + OWTAIL);  // [4][256]
    float* part_s  = (float*)(sm + OPART);   // [64][4]

    const int tid = threadIdx.x;
    const int wid = tid >> 5;
    const int lane = tid & 31;
    const int bz = blockIdx.z;
    const int b = bz >> 2, n = bz & 3;
    const int p0 = blockIdx.y * 4;
    const int a0 = blockIdx.x * 16;

    const int mwarp = (wid & 1) * 32;
    const int nwarp = (wid >> 1) * 64;

    // producer group: wid>>1 -> 4 groups of 2 warps
    const int group = wid >> 1;

    // epilogue tables
    bmid_s[tid] = bmid[n * H_ + tid];
    wout_s[tid] = Wout[n * H_ + tid];
#pragma unroll
    for (int q = 0; q < 4; q++) {
        const int i = q * NTHR + tid;
        wtail_s[i] = Wmid[(n * (H_ + NC_) + H_ + (i >> 8)) * H_ + (i & 255)];
    }

    // coalesced build mapping: group = 64 threads, 4 lanes per row-col,
    // row = pp*16 + brow0  =>  p = p0 + pp, a = a0 + brow0 (invariant!)
    const int gt = (wid & 1) * 32 + lane;   // 0..63 within group
    const int brow0 = gt >> 2;              // a-index 0..15
    const int bk4 = (gt & 3) * 4;
    const float* hp_base = g_hp + (b * L_ + p0) * H_;
    const float* ha_row  = g_ha + ((b * L_ + a0 + brow0) * NC_ + n) * H_;

    // lane-constant ldmatrix address offsets
    const uint32_t a_off = (uint32_t)((mwarp + (lane & 15)) * ROWB + ((lane >> 4) << 4));
    const uint32_t b_off = (uint32_t)((nwarp + (lane & 7) + ((lane & 16) ? 8 : 0)) * ROWB
                                      + ((lane & 8) ? 16 : 0));

    // build 16 k-values of chunk c at k-offset qoff into buffer buf
    auto buildX_part = [&](int c, int buf, int qoff) {
        const int kg = c * KCH + qoff + bk4;
        const float4 v = *(const float4*)(ha_row + kg);      // invariant over pp
        const float* up = hp_base + kg;                      // advances by H_
        uint32_t dst = base + OXB(buf)
                     + (uint32_t)(brow0 * ROWB + (qoff + bk4) * 2);
#pragma unroll
        for (int pp = 0; pp < 4; pp++) {
            const float4 u = *(const float4*)(up + pp * H_);
            const float x0 = htanh(u.x + v.x);
            const float x1 = htanh(u.y + v.y);
            const float x2 = htanh(u.z + v.z);
            const float x3 = htanh(u.w + v.w);
            sts64(dst, f16pack(x0, x1), f16pack(x2, x3));
            dst += 16 * ROWB;
        }
    };

    auto copyW = [&](int c, int buf) {
        const char* src = g_w_img + (size_t)(n * NCHUNK + c) * WIMG_BYTES;
        const uint32_t dst = base + OWB(buf);
#pragma unroll
        for (int i = 0; i < 9; i++) {
            const int e = i * NTHR + tid;           // 2304 x 16B
            cp_async16(dst + e * 16, src + (size_t)e * 16);
        }
        cp_commit();
    };

    float acc[2][8][4];
#pragma unroll
    for (int t = 0; t < 2; t++)
#pragma unroll
        for (int q = 0; q < 8; q++)
#pragma unroll
            for (int r = 0; r < 4; r++) acc[t][q][r] = 0.0f;

    // one k16-step: 16 independent MMAs
    auto mma_ks = [&](int ks, uint32_t xb, uint32_t wb) {
        uint32_t A0[4], A1[4], BH[4][4];
        const uint32_t kb = (uint32_t)(ks * 32);
        ldsm4(A0, xb + a_off + kb);
        ldsm4(A1, xb + a_off + 16 * ROWB + kb);
#pragma unroll
        for (int q = 0; q < 4; q++)
            ldsm4(BH[q], wb + b_off + q * 16 * ROWB + kb);
#pragma unroll
        for (int q2 = 0; q2 < 8; q2++) {
            const uint32_t* bq = &BH[q2 >> 1][(q2 & 1) * 2];
            mma16816(acc[0][q2], A0, bq);
            mma16816(acc[1][q2], A1, bq);
        }
    };

    // ---- prologue: each group builds its quarter of chunk 0 ----
    copyW(0, 0);
    buildX_part(0, 0, group * 16);
    cp_wait_all();
    __syncthreads();

#pragma unroll 1
    for (int c = 0; c < NCHUNK; c++) {
        const int cur = c & 1;
        const uint32_t xb = base + OXB(cur);
        const uint32_t wb = base + OWB(cur);
        const bool more = (c < NCHUNK - 1);
        if (more) copyW(c + 1, cur ^ 1);
        mma_ks(0, xb, wb);
        if (more && group == 0) buildX_part(c + 1, cur ^ 1, 0);
        mma_ks(1, xb, wb);
        if (more && group == 1) buildX_part(c + 1, cur ^ 1, 16);
        if (more && group == 3) buildX_part(c + 1, cur ^ 1, 48);
        mma_ks(2, xb, wb);
        if (more && group == 2) buildX_part(c + 1, cur ^ 1, 32);
        mma_ks(3, xb, wb);
        if (more) {
            cp_wait_all();
            __syncthreads();
        }
    }

    // ---- epilogue: +bs-tail +bmid, tanh, dot Wout, reduce over N ----
    const int g = lane >> 2;
    float bsv[2][2][4];
#pragma unroll
    for (int t = 0; t < 2; t++)
#pragma unroll
        for (int h = 0; h < 2; h++) {
            const int row = mwarp + t * 16 + g + h * 8;
            const float* bsp = bscore
                + ((b * L_ + p0 + (row >> 4)) * NC_) * L_ + a0 + (row & 15);
#pragma unroll
            for (int ct = 0; ct < 4; ct++) bsv[t][h][ct] = bsp[ct * L_];
        }

    float part[2][2] = {{0.0f, 0.0f}, {0.0f, 0.0f}};
#pragma unroll
    for (int q2 = 0; q2 < 8; q2++) {
        const int j0 = nwarp + q2 * 8 + (lane & 3) * 2;
        const float bm0 = bmid_s[j0], bm1 = bmid_s[j0 + 1];
        const float wo0 = wout_s[j0], wo1 = wout_s[j0 + 1];
        float wt0[4], wt1[4];
#pragma unroll
        for (int ct = 0; ct < 4; ct++) {
            wt0[ct] = wtail_s[ct * 256 + j0];
            wt1[ct] = wtail_s[ct * 256 + j0 + 1];
        }
#pragma unroll
        for (int t = 0; t < 2; t++)
#pragma unroll
            for (int h = 0; h < 2; h++) {
                float v0 = acc[t][q2][h * 2 + 0] + bm0;
                float v1 = acc[t][q2][h * 2 + 1] + bm1;
#pragma unroll
                for (int ct = 0; ct < 4; ct++) {
                    v0 = fmaf(bsv[t][h][ct], wt0[ct], v0);
                    v1 = fmaf(bsv[t][h][ct], wt1[ct], v1);
                }
                part[t][h] = fmaf(htanh(v0), wo0, part[t][h]);
                part[t][h] = fmaf(htanh(v1), wo1, part[t][h]);
            }
    }
#pragma unroll
    for (int t = 0; t < 2; t++)
#pragma unroll
        for (int h = 0; h < 2; h++) {
            float v = part[t][h];
            v += __shfl_xor_sync(0xFFFFFFFFu, v, 1, 4);
            v += __shfl_xor_sync(0xFFFFFFFFu, v, 2, 4);
            if ((lane & 3) == 0) {
                const int row = mwarp + t * 16 + g + h * 8;
                part_s[row * 4 + (wid >> 1)] = v;
            }
        }
    __syncthreads();

    if (tid < 64) {
        const float s = part_s[tid * 4] + part_s[tid * 4 + 1]
                      + part_s[tid * 4 + 2] + part_s[tid * 4 + 3];
        const int p = p0 + (tid >> 4);
        const int a = a0 + (tid & 15);
        out[((b * L_ + p) * NC_ + n) * L_ + a] = s;
    }
}

// ---------------------------------------------------------------------------
// Launch
// ---------------------------------------------------------------------------
extern "C" void kernel_launch(void* const* d_in, const int* in_sizes, int n_in,
                              void* d_out, int out_size) {
    const float* seq    = (const float*)d_in[0];
    const float* bscore = (const float*)d_in[1];
    const float* Wp     = (const float*)d_in[2];
    const float* bp     = (const float*)d_in[3];
    const float* Wa     = (const float*)d_in[4];
    const float* ba     = (const float*)d_in[5];
    const float* Wmid   = (const float*)d_in[6];
    const float* bmid   = (const float*)d_in[7];
    const float* Wout   = (const float*)d_in[8];
    float* out = (float*)d_out;

    prep_kernel<<<PREP_BLOCKS, 256>>>(seq, Wp, bp, Wa, ba, Wmid);

    cudaFuncSetAttribute(refine_kernel,
                         cudaFuncAttributeMaxDynamicSharedMemorySize, SMEM_BYTES);
    refine_kernel<<<dim3(L_ / 16, L_ / 4, B_ * NC_), NTHR, SMEM_BYTES>>>(
        bscore, Wmid, bmid, Wout, out);
}